// round 11
// baseline (speedup 1.0000x reference)
#include <cuda_runtime.h>
#include <cuda_bf16.h>

#define WIN     9
#define EDGE    4
#define B_MAX   131072
#define T_BINS  2048
#define TILES   256
#define TILEQ   512

__device__ int   g_idx[B_MAX];
__device__ int   g_perm[B_MAX];
__device__ float g_xs[B_MAX];                  // x pre-gathered into sorted order
__device__ int   g_tilehist[TILES * T_BINS];   // [tile][bin] counts -> in-bin tile offsets
__device__ int   g_bintot[T_BINS];
__device__ int   g_binbase[T_BINS];

// ---------- nearest-anchor index: analytic + exact fp32 argmin verify ----------
__device__ __forceinline__ int nearest_idx(float xv, const float* __restrict__ etab, int T)
{
    const float e0 = __ldg(&etab[0]);
    const float eN = __ldg(&etab[T - 1]);
    const float inv_step = (float)(T - 1) / (eN - e0);
    int i0 = (int)floorf((xv - e0) * inv_step);
    int idx = 0;
    float best = 3.4e38f;
    #pragma unroll
    for (int k = 0; k < 4; k++) {
        int cc = min(max(i0 - 1 + k, 0), T - 1);
        float d = xv - __ldg(&etab[cc]);
        d *= d;
        if (d < best) { best = d; idx = cc; }   // strict '<' == argmin first-occurrence
    }
    return idx;
}

// ---------- pass 1: per-tile smem histogram + g_idx (coalesced hist writes) ----------
__global__ __launch_bounds__(256)
void k_hist(const float* __restrict__ x, const float* __restrict__ etab, int B, int T)
{
    __shared__ int h[T_BINS];
    const int t = blockIdx.x;
    for (int i = threadIdx.x; i < T_BINS; i += 256) h[i] = 0;
    __syncthreads();

    const int q0 = t * TILEQ;
    #pragma unroll
    for (int i = threadIdx.x; i < TILEQ; i += 256) {
        int q = q0 + i;
        if (q < B) {
            int idx = nearest_idx(x[q], etab, T);
            g_idx[q] = idx;
            atomicAdd(&h[idx], 1);
        }
    }
    __syncthreads();
    for (int i = threadIdx.x; i < T_BINS; i += 256)
        g_tilehist[t * T_BINS + i] = h[i];
}

// ---------- pass 2: warp-per-bin exclusive scan over tiles (2048-way parallel) ----------
__global__ __launch_bounds__(256)
void k_scan()
{
    const int lane = threadIdx.x & 31;
    const int warp = threadIdx.x >> 5;
    const int bin  = blockIdx.x * 8 + warp;      // grid = 256 -> 2048 bins

    int run = 0;
    #pragma unroll
    for (int c = 0; c < TILES; c += 32) {
        int t = c + lane;
        int v = g_tilehist[t * T_BINS + bin];
        int inc = v;
        #pragma unroll
        for (int off = 1; off < 32; off <<= 1) {
            int n = __shfl_up_sync(0xffffffffu, inc, off);
            if (lane >= off) inc += n;
        }
        g_tilehist[t * T_BINS + bin] = run + (inc - v);   // exclusive offset
        run += __shfl_sync(0xffffffffu, inc, 31);
    }
    if (lane == 0) g_bintot[bin] = run;
}

// ---------- pass 3: exclusive scan over 2048 bin totals (one block) ----------
__global__ __launch_bounds__(1024)
void k_binscan()
{
    __shared__ int s[1024];
    int i = threadIdx.x;
    int a = g_bintot[2 * i];
    int b = g_bintot[2 * i + 1];
    s[i] = a + b;
    #pragma unroll
    for (int off = 1; off < 1024; off <<= 1) {
        __syncthreads();
        int v = (i >= off) ? s[i - off] : 0;
        __syncthreads();
        s[i] += v;
    }
    __syncthreads();
    int excl_pair = s[i] - (a + b);
    g_binbase[2 * i]     = excl_pair;
    g_binbase[2 * i + 1] = excl_pair + a;
}

// ---------- pass 4: contention-free scatter (smem rank) + x pre-gather ----------
__global__ __launch_bounds__(256)
void k_scatter(const float* __restrict__ x, int B)
{
    __shared__ int r[T_BINS];
    const int t = blockIdx.x;
    for (int i = threadIdx.x; i < T_BINS; i += 256) r[i] = 0;
    __syncthreads();

    const int q0 = t * TILEQ;
    #pragma unroll
    for (int i = threadIdx.x; i < TILEQ; i += 256) {
        int q = q0 + i;
        if (q < B) {
            int bin = g_idx[q];
            int lr  = atomicAdd(&r[bin], 1);
            int pos = g_binbase[bin] + g_tilehist[t * T_BINS + bin] + lr;
            g_perm[pos] = q;
            g_xs[pos]   = x[q];
        }
    }
}

// ---------- pass 5: block-per-bin, rows register-resident, zero gather ----------
__global__ __launch_bounds__(128, 4)
void k_main(const float* __restrict__ etab,
            const float* __restrict__ tctab,
            const float* __restrict__ vtab,
            float* __restrict__ out,
            int B, int T)
{
    const int bin = blockIdx.x;
    const int cnt = g_bintot[bin];
    if (cnt == 0) return;
    const int start = g_binbase[bin];

    const int lane = threadIdx.x & 31;
    const int warp = threadIdx.x >> 5;
    const int qsel = lane >> 3;        // 0..3
    const int sub  = lane & 7;         // 0..7: 16B chunk pair of D=64

    const float tc = __ldg(&tctab[bin]);               // UNCLIPPED idx (matches ref)
    const int base = min(max(bin, EDGE), T - 1 - EDGE) - EDGE;

    // window anchor values (all lanes; broadcast loads)
    float ev[WIN];
    #pragma unroll
    for (int j = 0; j < WIN; j++) ev[j] = __ldg(&etab[base + j]);

    // register-resident rows: this lane's two 16B chunks of each of the 9 rows
    const float4* vt = (const float4*)vtab;
    float4 r0[WIN], r1[WIN];
    #pragma unroll
    for (int j = 0; j < WIN; j++) {
        const float4* row = vt + (size_t)(base + j) * 16;
        r0[j] = __ldg(row + sub);
        r1[j] = __ldg(row + 8 + sub);
    }

    for (int it = warp * 4; it < cnt; it += 16) {      // 4 warps x 4 queries
        float wv[WIN];
        int gq = -1;
        if (lane < 4 && it + lane < cnt) {
            const int p = start + it + lane;
            gq = g_perm[p];
            const float xv = g_xs[p];                  // coalesced sorted-x read
            float m = -3.4e38f;
            #pragma unroll
            for (int j = 0; j < WIN; j++) {
                float d = xv - ev[j];
                float l = -(d * d) * tc;
                wv[j] = l;
                m = fmaxf(m, l);
            }
            float sum = 0.0f;
            #pragma unroll
            for (int j = 0; j < WIN; j++) {
                float pp = __expf(wv[j] - m);
                wv[j] = pp;
                sum += pp;
            }
            const float inv = __frcp_rn(sum);
            #pragma unroll
            for (int j = 0; j < WIN; j++) wv[j] *= inv;
        }

        gq = __shfl_sync(0xffffffffu, gq, qsel);
        #pragma unroll
        for (int j = 0; j < WIN; j++) wv[j] = __shfl_sync(0xffffffffu, wv[j], qsel);

        if (gq >= 0) {
            float4 a0 = make_float4(0.f, 0.f, 0.f, 0.f);
            float4 a1 = make_float4(0.f, 0.f, 0.f, 0.f);
            #pragma unroll
            for (int j = 0; j < WIN; j++) {
                float wj = wv[j];
                a0.x = fmaf(wj, r0[j].x, a0.x);
                a0.y = fmaf(wj, r0[j].y, a0.y);
                a0.z = fmaf(wj, r0[j].z, a0.z);
                a0.w = fmaf(wj, r0[j].w, a0.w);
                a1.x = fmaf(wj, r1[j].x, a1.x);
                a1.y = fmaf(wj, r1[j].y, a1.y);
                a1.z = fmaf(wj, r1[j].z, a1.z);
                a1.w = fmaf(wj, r1[j].w, a1.w);
            }
            float4* o = (float4*)(out + (size_t)gq * 64);
            __stcs(o + sub,     a0);
            __stcs(o + 8 + sub, a1);
        }
    }
}

extern "C" void kernel_launch(void* const* d_in, const int* in_sizes, int n_in,
                              void* d_out, int out_size)
{
    const float* x     = (const float*)d_in[0];   // [B,1]
    const float* etab  = (const float*)d_in[1];   // [T,1]
    const float* tctab = (const float*)d_in[2];   // [T,1]
    const float* vtab  = (const float*)d_in[3];   // [T,D]
    float* out = (float*)d_out;

    const int B = in_sizes[0];                    // 131072
    const int T = in_sizes[1];                    // 2048

    k_hist   <<<TILES, 256>>>(x, etab, B, T);
    k_scan   <<<T_BINS / 8, 256>>>();
    k_binscan<<<1, 1024>>>();
    k_scatter<<<TILES, 256>>>(x, B);
    k_main   <<<T_BINS, 128>>>(etab, tctab, vtab, out, B, T);
}